// round 1
// baseline (speedup 1.0000x reference)
#include <cuda_runtime.h>
#include <math.h>

#define BATCH 4
#define SEQ   2048
#define DIM   768
#define NH    12
#define HDIM  64
#define FFDIM (4*DIM)
#define ROWS  (BATCH*SEQ)   /* 8192 */

// ---------------- scratch (no cudaMalloc allowed) ----------------
__device__ float g_q[(size_t)BATCH*NH*SEQ*HDIM];
__device__ float g_k[(size_t)BATCH*NH*SEQ*HDIM];
__device__ float g_v[(size_t)BATCH*NH*SEQ*HDIM];
__device__ float g_attn[(size_t)ROWS*DIM];
__device__ float g_t1[(size_t)ROWS*DIM];
__device__ float g_h[(size_t)ROWS*DIM];
__device__ float g_ff[(size_t)ROWS*FFDIM];

// ---------------- SGEMM 128x128x8, 256 threads, 8x8 micro ----------------
// MODE 0: C = A@B + bias
// MODE 1: QKV store: C viewed as [B,H,S,HD], row=b*S+s, col=h*HD+hd
// MODE 2: C = gelu(A@B + bias)      (exact gelu)
// MODE 3: C = A@B + bias + res[row*N+col]
template<int MODE>
__global__ __launch_bounds__(256) void sgemm(const float* __restrict__ A,
                                             const float* __restrict__ B,
                                             const float* __restrict__ bias,
                                             const float* __restrict__ res,
                                             float* __restrict__ C,
                                             int M, int N, int K)
{
    __shared__ float As[8][132];
    __shared__ float Bs[8][132];

    const int tid = threadIdx.x;
    const int tx  = tid & 15;
    const int ty  = tid >> 4;
    const int bm  = blockIdx.y * 128;
    const int bn  = blockIdx.x * 128;

    const int arow = tid >> 1;
    const int acol = (tid & 1) * 4;
    const int bkr  = tid >> 5;
    const int bcol = (tid & 31) * 4;

    const float* Aptr = A + (size_t)(bm + arow) * K + acol;
    const float* Bptr = B + (size_t)bkr * N + bn + bcol;

    float acc[8][8];
#pragma unroll
    for (int i = 0; i < 8; ++i)
#pragma unroll
        for (int j = 0; j < 8; ++j) acc[i][j] = 0.f;

    const int nk = K >> 3;
    for (int t = 0; t < nk; ++t) {
        float4 a4 = *(const float4*)Aptr;
        float4 b4 = *(const float4*)Bptr;
        As[acol + 0][arow] = a4.x;
        As[acol + 1][arow] = a4.y;
        As[acol + 2][arow] = a4.z;
        As[acol + 3][arow] = a4.w;
        *(float4*)&Bs[bkr][bcol] = b4;
        __syncthreads();

#pragma unroll
        for (int k = 0; k < 8; ++k) {
            float4 a0 = *(const float4*)&As[k][ty * 4];
            float4 a1 = *(const float4*)&As[k][ty * 4 + 64];
            float4 b0 = *(const float4*)&Bs[k][tx * 4];
            float4 b1 = *(const float4*)&Bs[k][tx * 4 + 64];
            float ar[8] = {a0.x, a0.y, a0.z, a0.w, a1.x, a1.y, a1.z, a1.w};
            float br[8] = {b0.x, b0.y, b0.z, b0.w, b1.x, b1.y, b1.z, b1.w};
#pragma unroll
            for (int i = 0; i < 8; ++i)
#pragma unroll
                for (int j = 0; j < 8; ++j)
                    acc[i][j] = fmaf(ar[i], br[j], acc[i][j]);
        }
        __syncthreads();
        Aptr += 8;
        Bptr += (size_t)8 * N;
    }

    // epilogue
#pragma unroll
    for (int i = 0; i < 8; ++i) {
        const int row = bm + ((i < 4) ? (ty * 4 + i) : (64 + ty * 4 + i - 4));
#pragma unroll
        for (int jc = 0; jc < 2; ++jc) {
            const int col = bn + tx * 4 + jc * 64;
            float4 v;
            v.x = acc[i][jc * 4 + 0] + bias[col + 0];
            v.y = acc[i][jc * 4 + 1] + bias[col + 1];
            v.z = acc[i][jc * 4 + 2] + bias[col + 2];
            v.w = acc[i][jc * 4 + 3] + bias[col + 3];
            if (MODE == 2) {
                v.x = 0.5f * v.x * (1.f + erff(v.x * 0.70710678118654752f));
                v.y = 0.5f * v.y * (1.f + erff(v.y * 0.70710678118654752f));
                v.z = 0.5f * v.z * (1.f + erff(v.z * 0.70710678118654752f));
                v.w = 0.5f * v.w * (1.f + erff(v.w * 0.70710678118654752f));
            }
            if (MODE == 3) {
                float4 r = *(const float4*)&res[(size_t)row * N + col];
                v.x += r.x; v.y += r.y; v.z += r.z; v.w += r.w;
            }
            if (MODE == 1) {
                const int b = row / SEQ, s = row % SEQ;
                const int h = col / HDIM, hd = col % HDIM;
                *(float4*)&C[(((size_t)b * NH + h) * SEQ + s) * HDIM + hd] = v;
            } else {
                *(float4*)&C[(size_t)row * N + col] = v;
            }
        }
    }
}

// ---------------- flash attention: BM=128 q-rows, BN=64 keys, 256 thr ----------------
// smem plan (floats):
//  Qt[64][132]  d-major Q (scaled)
//  Kt[64][68]   d-major K tile
//  Vs[64][68]   row-major V tile
//  Pt[64][132]  k-major P tile
//  red[128][17] reduction scratch
//  m_i[128] l_i[128] corr[128] mb[64]
#define ATTN_SMEM_FLOATS (64*132 + 64*68 + 64*68 + 64*132 + 128*17 + 128*3 + 64)

__global__ __launch_bounds__(256) void attn_kernel(const float* __restrict__ q,
                                                   const float* __restrict__ k,
                                                   const float* __restrict__ v,
                                                   const int* __restrict__ mask,
                                                   float* __restrict__ out)
{
    extern __shared__ float sm[];
    float* Qt   = sm;
    float* Kt   = Qt + 64 * 132;
    float* Vs   = Kt + 64 * 68;
    float* Pt   = Vs + 64 * 68;
    float* red  = Pt + 64 * 132;
    float* m_i  = red + 128 * 17;
    float* l_i  = m_i + 128;
    float* corr = l_i + 128;
    float* mb   = corr + 128;

    const int tid = threadIdx.x;
    const int tx  = tid & 15;
    const int ty  = tid >> 4;

    const int blk   = blockIdx.x;
    const int qtile = blk & 15;     // S/128 = 16 tiles
    const int bh    = blk >> 4;     // 0..47
    const int b     = bh / NH;
    const int h     = bh % NH;
    const float scale = 0.125f;     // HD^-0.5

    const size_t base = (size_t)bh * SEQ * HDIM;
    const int q0 = qtile * 128;

    // load Q (scaled) into d-major smem
    {
        const int d = (tid & 15) * 4;
#pragma unroll
        for (int it = 0; it < 8; ++it) {
            const int r = (tid >> 4) + it * 16;
            float4 qv = *(const float4*)&q[base + (size_t)(q0 + r) * HDIM + d];
            Qt[(d + 0) * 132 + r] = qv.x * scale;
            Qt[(d + 1) * 132 + r] = qv.y * scale;
            Qt[(d + 2) * 132 + r] = qv.z * scale;
            Qt[(d + 3) * 132 + r] = qv.w * scale;
        }
    }
    if (tid < 128) { m_i[tid] = -1e30f; l_i[tid] = 0.f; }

    float acc[8][4];
#pragma unroll
    for (int i = 0; i < 8; ++i)
#pragma unroll
        for (int j = 0; j < 4; ++j) acc[i][j] = 0.f;

    __syncthreads();

    for (int kt = 0; kt < SEQ / 64; ++kt) {
        const int k0 = kt * 64;
        // load K (d-major) and V (row-major)
        {
            const int d = (tid & 15) * 4;
            const int rb = tid >> 4;
#pragma unroll
            for (int it = 0; it < 4; ++it) {
                const int rr = rb + it * 16;
                float4 kv = *(const float4*)&k[base + (size_t)(k0 + rr) * HDIM + d];
                Kt[(d + 0) * 68 + rr] = kv.x;
                Kt[(d + 1) * 68 + rr] = kv.y;
                Kt[(d + 2) * 68 + rr] = kv.z;
                Kt[(d + 3) * 68 + rr] = kv.w;
                float4 vv = *(const float4*)&v[base + (size_t)(k0 + rr) * HDIM + d];
                *(float4*)&Vs[rr * 68 + d] = vv;
            }
        }
        if (tid < 64) mb[tid] = mask[b * SEQ + k0 + tid] ? 0.f : -1e30f;
        __syncthreads();

        // S = Q @ K^T
        float s[8][4];
#pragma unroll
        for (int i = 0; i < 8; ++i)
#pragma unroll
            for (int j = 0; j < 4; ++j) s[i][j] = 0.f;

#pragma unroll 4
        for (int d = 0; d < 64; ++d) {
            float4 a0 = *(const float4*)&Qt[d * 132 + ty * 4];
            float4 a1 = *(const float4*)&Qt[d * 132 + ty * 4 + 64];
            float4 bk4 = *(const float4*)&Kt[d * 68 + tx * 4];
            float ar[8] = {a0.x, a0.y, a0.z, a0.w, a1.x, a1.y, a1.z, a1.w};
            float br[4] = {bk4.x, bk4.y, bk4.z, bk4.w};
#pragma unroll
            for (int i = 0; i < 8; ++i)
#pragma unroll
                for (int j = 0; j < 4; ++j)
                    s[i][j] = fmaf(ar[i], br[j], s[i][j]);
        }

        // mask bias + row-max partials
#pragma unroll
        for (int i = 0; i < 8; ++i) {
            const int row = (i < 4) ? (ty * 4 + i) : (64 + ty * 4 + i - 4);
            float mx = -1e30f;
#pragma unroll
            for (int j = 0; j < 4; ++j) {
                s[i][j] += mb[tx * 4 + j];
                mx = fmaxf(mx, s[i][j]);
            }
            red[row * 17 + tx] = mx;
        }
        __syncthreads();

        if (tid < 128) {
            float mx = red[tid * 17];
#pragma unroll
            for (int t = 1; t < 16; ++t) mx = fmaxf(mx, red[tid * 17 + t]);
            const float mnew = fmaxf(m_i[tid], mx);
            corr[tid] = __expf(m_i[tid] - mnew);
            m_i[tid] = mnew;
        }
        __syncthreads();

        // P = exp(S - m), accumulate l, rescale acc, stage P (k-major)
#pragma unroll
        for (int i = 0; i < 8; ++i) {
            const int row = (i < 4) ? (ty * 4 + i) : (64 + ty * 4 + i - 4);
            const float mn = m_i[row];
            const float c  = corr[row];
            float sum = 0.f;
#pragma unroll
            for (int j = 0; j < 4; ++j) {
                const float p = __expf(s[i][j] - mn);
                sum += p;
                acc[i][j] *= c;
                Pt[(tx * 4 + j) * 132 + row] = p;
            }
            red[row * 17 + tx] = sum;
        }
        __syncthreads();

        if (tid < 128) {
            float sum = 0.f;
#pragma unroll
            for (int t = 0; t < 16; ++t) sum += red[tid * 17 + t];
            l_i[tid] = l_i[tid] * corr[tid] + sum;
        }

        // acc += P @ V
#pragma unroll 2
        for (int kk = 0; kk < 64; ++kk) {
            float4 p0 = *(const float4*)&Pt[kk * 132 + ty * 4];
            float4 p1 = *(const float4*)&Pt[kk * 132 + ty * 4 + 64];
            float4 vv = *(const float4*)&Vs[kk * 68 + tx * 4];
            float pr[8] = {p0.x, p0.y, p0.z, p0.w, p1.x, p1.y, p1.z, p1.w};
            float vr[4] = {vv.x, vv.y, vv.z, vv.w};
#pragma unroll
            for (int i = 0; i < 8; ++i)
#pragma unroll
                for (int j = 0; j < 4; ++j)
                    acc[i][j] = fmaf(pr[i], vr[j], acc[i][j]);
        }
        __syncthreads();
    }

    // write out to [B,S,D] with col = h*HD + c
#pragma unroll
    for (int i = 0; i < 8; ++i) {
        const int row = (i < 4) ? (ty * 4 + i) : (64 + ty * 4 + i - 4);
        const float inv = 1.f / l_i[row];
        float4 o;
        o.x = acc[i][0] * inv;
        o.y = acc[i][1] * inv;
        o.z = acc[i][2] * inv;
        o.w = acc[i][3] * inv;
        *(float4*)&out[(size_t)(b * SEQ + q0 + row) * DIM + h * HDIM + tx * 4] = o;
    }
}

// ---------------- LayerNorm: one block per row ----------------
__global__ __launch_bounds__(256) void ln_kernel(const float* __restrict__ in,
                                                 const float* __restrict__ gam,
                                                 const float* __restrict__ bet,
                                                 float* __restrict__ out)
{
    const int row = blockIdx.x;
    const int tid = threadIdx.x;
    const float* x = in + (size_t)row * DIM;

    float v[3];
    float s = 0.f, s2 = 0.f;
#pragma unroll
    for (int i = 0; i < 3; ++i) {
        v[i] = x[tid + i * 256];
        s  += v[i];
        s2 += v[i] * v[i];
    }
#pragma unroll
    for (int o = 16; o > 0; o >>= 1) {
        s  += __shfl_xor_sync(0xffffffffu, s,  o);
        s2 += __shfl_xor_sync(0xffffffffu, s2, o);
    }
    __shared__ float sh[18];
    const int wid = tid >> 5, lane = tid & 31;
    if (lane == 0) { sh[wid] = s; sh[8 + wid] = s2; }
    __syncthreads();
    if (tid == 0) {
        float ts = 0.f, ts2 = 0.f;
#pragma unroll
        for (int w = 0; w < 8; ++w) { ts += sh[w]; ts2 += sh[8 + w]; }
        const float mu  = ts * (1.f / DIM);
        const float var = ts2 * (1.f / DIM) - mu * mu;
        sh[16] = mu;
        sh[17] = rsqrtf(var + 1e-6f);
    }
    __syncthreads();
    const float mu = sh[16], rstd = sh[17];
#pragma unroll
    for (int i = 0; i < 3; ++i) {
        const int d = tid + i * 256;
        out[(size_t)row * DIM + d] = (v[i] - mu) * rstd * gam[d] + bet[d];
    }
}

// ---------------- launch ----------------
extern "C" void kernel_launch(void* const* d_in, const int* in_sizes, int n_in,
                              void* d_out, int out_size)
{
    const float* x    = (const float*)d_in[0];
    const int*   mask = (const int*)  d_in[1];
    const float* Wq   = (const float*)d_in[2];
    const float* bq   = (const float*)d_in[3];
    const float* Wk   = (const float*)d_in[4];
    const float* bk   = (const float*)d_in[5];
    const float* Wv   = (const float*)d_in[6];
    const float* bv   = (const float*)d_in[7];
    const float* Wo   = (const float*)d_in[8];
    const float* bo   = (const float*)d_in[9];
    const float* W1   = (const float*)d_in[10];
    const float* b1   = (const float*)d_in[11];
    const float* W2   = (const float*)d_in[12];
    const float* b2   = (const float*)d_in[13];
    const float* g1   = (const float*)d_in[14];
    const float* be1  = (const float*)d_in[15];
    const float* g2   = (const float*)d_in[16];
    const float* be2  = (const float*)d_in[17];
    float* out = (float*)d_out;

    float *q, *k, *v, *attn, *t1, *h, *ff;
    cudaGetSymbolAddress((void**)&q,    g_q);
    cudaGetSymbolAddress((void**)&k,    g_k);
    cudaGetSymbolAddress((void**)&v,    g_v);
    cudaGetSymbolAddress((void**)&attn, g_attn);
    cudaGetSymbolAddress((void**)&t1,   g_t1);
    cudaGetSymbolAddress((void**)&h,    g_h);
    cudaGetSymbolAddress((void**)&ff,   g_ff);

    const dim3 gD(DIM / 128, ROWS / 128);     // (6, 64)
    const dim3 gF(FFDIM / 128, ROWS / 128);   // (24, 64)

    // QKV projections, stored as [B,H,S,HD]
    sgemm<1><<<gD, 256>>>(x, Wq, bq, nullptr, q, ROWS, DIM, DIM);
    sgemm<1><<<gD, 256>>>(x, Wk, bk, nullptr, k, ROWS, DIM, DIM);
    sgemm<1><<<gD, 256>>>(x, Wv, bv, nullptr, v, ROWS, DIM, DIM);

    // flash attention
    const int smem_bytes = ATTN_SMEM_FLOATS * (int)sizeof(float);
    cudaFuncSetAttribute(attn_kernel, cudaFuncAttributeMaxDynamicSharedMemorySize, smem_bytes);
    attn_kernel<<<BATCH * NH * (SEQ / 128), 256, smem_bytes>>>(q, k, v, mask, attn);

    // O projection + residual, LN1
    sgemm<3><<<gD, 256>>>(attn, Wo, bo, x, t1, ROWS, DIM, DIM);
    ln_kernel<<<ROWS, 256>>>(t1, g1, be1, h);

    // FFN
    sgemm<2><<<gF, 256>>>(h, W1, b1, nullptr, ff, ROWS, FFDIM, DIM);
    sgemm<3><<<gD, 256>>>(ff, W2, b2, h, t1, ROWS, DIM, FFDIM);
    ln_kernel<<<ROWS, 256>>>(t1, g2, be2, out);
}

// round 2
// speedup vs baseline: 1.8223x; 1.8223x over previous
#include <cuda_runtime.h>
#include <math.h>

#define BATCH 4
#define SEQ   2048
#define DIM   768
#define NH    12
#define HDIM  64
#define FFDIM (4*DIM)
#define ROWS  (BATCH*SEQ)   /* 8192 */

// ---------------- scratch (no cudaMalloc allowed) ----------------
__device__ float g_q[(size_t)BATCH*NH*SEQ*HDIM];
__device__ float g_k[(size_t)BATCH*NH*SEQ*HDIM];
__device__ float g_v[(size_t)BATCH*NH*SEQ*HDIM];
__device__ float g_attn[(size_t)ROWS*DIM];
__device__ float g_t1[(size_t)ROWS*DIM];
__device__ float g_h[(size_t)ROWS*DIM];
__device__ float g_ff[(size_t)ROWS*FFDIM];

// ======================================================================
// TF32 tensor-core GEMM: 128x128 CTA tile, BK=32, 256 threads (8 warps,
// 2x4 warp grid, 64x32 warp tile), mma.sync.m16n8k8.tf32.
// MODE 0: C = A@B + bias
// MODE 1: QKV store: C viewed as [B,H,S,HD]
// MODE 2: C = gelu(A@B + bias)
// MODE 3: C = A@B + bias + res
// ======================================================================

#define SA 36     /* A smem row stride (floats): bank = lane, conflict-free */
#define SB 136    /* B smem row stride: 8*r+c perm, conflict-free */
#define ABUF (128*SA)          /* 4608 floats */
#define BBUF (32*SB)           /* 4352 floats */
#define BUFSZ (ABUF + BBUF)    /* 8960 floats per stage */

__device__ __forceinline__ unsigned f2tf(float f) {
    unsigned r;
    asm("cvt.rna.tf32.f32 %0, %1;" : "=r"(r) : "f"(f));
    return r;
}

__device__ __forceinline__ void mma_tf32(float* d, const unsigned* a, const unsigned* b) {
    asm volatile(
        "mma.sync.aligned.m16n8k8.row.col.f32.tf32.tf32.f32 "
        "{%0,%1,%2,%3}, {%4,%5,%6,%7}, {%8,%9}, {%0,%1,%2,%3};\n"
        : "+f"(d[0]), "+f"(d[1]), "+f"(d[2]), "+f"(d[3])
        : "r"(a[0]), "r"(a[1]), "r"(a[2]), "r"(a[3]), "r"(b[0]), "r"(b[1]));
}

template<int MODE>
__global__ __launch_bounds__(256) void tgemm(const float* __restrict__ A,
                                             const float* __restrict__ B,
                                             const float* __restrict__ bias,
                                             const float* __restrict__ res,
                                             float* __restrict__ C,
                                             int M, int N, int K)
{
    extern __shared__ float sm[];

    const int tid  = threadIdx.x;
    const int lane = tid & 31;
    const int warp = tid >> 5;
    const int wr   = warp >> 2;      // 0..1
    const int wn   = warp & 3;       // 0..3
    const int bm   = blockIdx.y * 128;
    const int bn   = blockIdx.x * 128;

    // gmem load assignments
    const int arow = tid >> 3;             // 0..31
    const int acol = (tid & 7) * 4;        // 0..28
    const int brow = tid >> 6;             // 0..3  (8 rows per pass -> 4 passes? no: tid/64 gives 0..3)
    // B: 32 rows x 128 cols, 256 thr * 4 passes * float4 = 4096. Use:
    //   per pass p: k = tid/32 + 8p, col = (tid%32)*4
    const int bkr  = tid >> 5;             // 0..7
    const int bcol = (tid & 31) * 4;

    float acc[4][4][4];
#pragma unroll
    for (int mt = 0; mt < 4; ++mt)
#pragma unroll
        for (int nt = 0; nt < 4; ++nt)
#pragma unroll
            for (int e = 0; e < 4; ++e) acc[mt][nt][e] = 0.f;

    const int nk = K >> 5;
    float4 ra[4], rb[4];

    // ---- load chunk 0 ----
    {
        const float* Ap = A + (size_t)(bm + arow) * K + acol;
        const float* Bp = B + (size_t)bkr * N + bn + bcol;
#pragma unroll
        for (int i = 0; i < 4; ++i) {
            ra[i] = *(const float4*)(Ap + (size_t)(32 * i) * K);
            rb[i] = *(const float4*)(Bp + (size_t)(8 * i) * N);
        }
    }
    // ---- stage chunk 0 -> buf 0 ----
    {
        float* As = sm;
        float* Bs = sm + ABUF;
#pragma unroll
        for (int i = 0; i < 4; ++i) {
            unsigned x = f2tf(ra[i].x), y = f2tf(ra[i].y), z = f2tf(ra[i].z), w = f2tf(ra[i].w);
            float4 v = make_float4(__uint_as_float(x), __uint_as_float(y),
                                   __uint_as_float(z), __uint_as_float(w));
            *(float4*)&As[(arow + 32 * i) * SA + acol] = v;
            x = f2tf(rb[i].x); y = f2tf(rb[i].y); z = f2tf(rb[i].z); w = f2tf(rb[i].w);
            v = make_float4(__uint_as_float(x), __uint_as_float(y),
                            __uint_as_float(z), __uint_as_float(w));
            *(float4*)&Bs[(bkr + 8 * i) * SB + bcol] = v;
        }
    }
    __syncthreads();

    for (int t = 0; t < nk; ++t) {
        // prefetch next chunk to regs
        if (t + 1 < nk) {
            const float* Ap = A + (size_t)(bm + arow) * K + (t + 1) * 32 + acol;
            const float* Bp = B + (size_t)((t + 1) * 32 + bkr) * N + bn + bcol;
#pragma unroll
            for (int i = 0; i < 4; ++i) {
                ra[i] = *(const float4*)(Ap + (size_t)(32 * i) * K);
                rb[i] = *(const float4*)(Bp + (size_t)(8 * i) * N);
            }
        }

        // compute on current buffer
        {
            const float* As = sm + (t & 1) * BUFSZ;
            const float* Bs = As + ABUF;
#pragma unroll
            for (int ks = 0; ks < 4; ++ks) {
                const int k0 = ks * 8 + (lane & 3);
                unsigned af[4][4], bf[4][2];
#pragma unroll
                for (int mt = 0; mt < 4; ++mt) {
                    const int m0 = wr * 64 + mt * 16 + (lane >> 2);
                    af[mt][0] = __float_as_uint(As[m0 * SA + k0]);
                    af[mt][1] = __float_as_uint(As[(m0 + 8) * SA + k0]);
                    af[mt][2] = __float_as_uint(As[m0 * SA + k0 + 4]);
                    af[mt][3] = __float_as_uint(As[(m0 + 8) * SA + k0 + 4]);
                }
#pragma unroll
                for (int nt = 0; nt < 4; ++nt) {
                    const int n0 = wn * 32 + nt * 8 + (lane >> 2);
                    bf[nt][0] = __float_as_uint(Bs[k0 * SB + n0]);
                    bf[nt][1] = __float_as_uint(Bs[(k0 + 4) * SB + n0]);
                }
#pragma unroll
                for (int mt = 0; mt < 4; ++mt)
#pragma unroll
                    for (int nt = 0; nt < 4; ++nt)
                        mma_tf32(acc[mt][nt], af[mt], bf[nt]);
            }
        }

        // stage next chunk
        if (t + 1 < nk) {
            float* As = sm + ((t + 1) & 1) * BUFSZ;
            float* Bs = As + ABUF;
#pragma unroll
            for (int i = 0; i < 4; ++i) {
                unsigned x = f2tf(ra[i].x), y = f2tf(ra[i].y), z = f2tf(ra[i].z), w = f2tf(ra[i].w);
                float4 v = make_float4(__uint_as_float(x), __uint_as_float(y),
                                       __uint_as_float(z), __uint_as_float(w));
                *(float4*)&As[(arow + 32 * i) * SA + acol] = v;
                x = f2tf(rb[i].x); y = f2tf(rb[i].y); z = f2tf(rb[i].z); w = f2tf(rb[i].w);
                v = make_float4(__uint_as_float(x), __uint_as_float(y),
                                __uint_as_float(z), __uint_as_float(w));
                *(float4*)&Bs[(bkr + 8 * i) * SB + bcol] = v;
            }
            __syncthreads();
        }
    }

    // ---- epilogue ----
#pragma unroll
    for (int mt = 0; mt < 4; ++mt) {
        const int row_lo = bm + wr * 64 + mt * 16 + (lane >> 2);
#pragma unroll
        for (int nt = 0; nt < 4; ++nt) {
            const int col = bn + wn * 32 + nt * 8 + (lane & 3) * 2;
#pragma unroll
            for (int half = 0; half < 2; ++half) {
                const int row = row_lo + half * 8;
                float2 v;
                v.x = acc[mt][nt][half * 2 + 0] + bias[col + 0];
                v.y = acc[mt][nt][half * 2 + 1] + bias[col + 1];
                if (MODE == 2) {
                    v.x = 0.5f * v.x * (1.f + erff(v.x * 0.70710678118654752f));
                    v.y = 0.5f * v.y * (1.f + erff(v.y * 0.70710678118654752f));
                }
                if (MODE == 3) {
                    float2 r = *(const float2*)&res[(size_t)row * N + col];
                    v.x += r.x; v.y += r.y;
                }
                if (MODE == 1) {
                    const int b = row / SEQ, s = row % SEQ;
                    const int h = col / HDIM, hd = col % HDIM;
                    *(float2*)&C[(((size_t)b * NH + h) * SEQ + s) * HDIM + hd] = v;
                } else {
                    *(float2*)&C[(size_t)row * N + col] = v;
                }
            }
        }
    }
}

#define GEMM_SMEM (2 * BUFSZ * (int)sizeof(float))   /* 71680 bytes */

// ---------------- flash attention: BM=128 q-rows, BN=64 keys, 256 thr ----------------
#define ATTN_SMEM_FLOATS (64*132 + 64*68 + 64*68 + 64*132 + 128*17 + 128*3 + 64)

__global__ __launch_bounds__(256) void attn_kernel(const float* __restrict__ q,
                                                   const float* __restrict__ k,
                                                   const float* __restrict__ v,
                                                   const int* __restrict__ mask,
                                                   float* __restrict__ out)
{
    extern __shared__ float sm[];
    float* Qt   = sm;
    float* Kt   = Qt + 64 * 132;
    float* Vs   = Kt + 64 * 68;
    float* Pt   = Vs + 64 * 68;
    float* red  = Pt + 64 * 132;
    float* m_i  = red + 128 * 17;
    float* l_i  = m_i + 128;
    float* corr = l_i + 128;
    float* mb   = corr + 128;

    const int tid = threadIdx.x;
    const int tx  = tid & 15;
    const int ty  = tid >> 4;

    const int blk   = blockIdx.x;
    const int qtile = blk & 15;
    const int bh    = blk >> 4;
    const int b     = bh / NH;
    const int h     = bh % NH;
    const float scale = 0.125f;

    const size_t base = (size_t)bh * SEQ * HDIM;
    const int q0 = qtile * 128;

    {
        const int d = (tid & 15) * 4;
#pragma unroll
        for (int it = 0; it < 8; ++it) {
            const int r = (tid >> 4) + it * 16;
            float4 qv = *(const float4*)&q[base + (size_t)(q0 + r) * HDIM + d];
            Qt[(d + 0) * 132 + r] = qv.x * scale;
            Qt[(d + 1) * 132 + r] = qv.y * scale;
            Qt[(d + 2) * 132 + r] = qv.z * scale;
            Qt[(d + 3) * 132 + r] = qv.w * scale;
        }
    }
    if (tid < 128) { m_i[tid] = -1e30f; l_i[tid] = 0.f; }

    float acc[8][4];
#pragma unroll
    for (int i = 0; i < 8; ++i)
#pragma unroll
        for (int j = 0; j < 4; ++j) acc[i][j] = 0.f;

    __syncthreads();

    for (int kt = 0; kt < SEQ / 64; ++kt) {
        const int k0 = kt * 64;
        {
            const int d = (tid & 15) * 4;
            const int rb = tid >> 4;
#pragma unroll
            for (int it = 0; it < 4; ++it) {
                const int rr = rb + it * 16;
                float4 kv = *(const float4*)&k[base + (size_t)(k0 + rr) * HDIM + d];
                Kt[(d + 0) * 68 + rr] = kv.x;
                Kt[(d + 1) * 68 + rr] = kv.y;
                Kt[(d + 2) * 68 + rr] = kv.z;
                Kt[(d + 3) * 68 + rr] = kv.w;
                float4 vv = *(const float4*)&v[base + (size_t)(k0 + rr) * HDIM + d];
                *(float4*)&Vs[rr * 68 + d] = vv;
            }
        }
        if (tid < 64) mb[tid] = mask[b * SEQ + k0 + tid] ? 0.f : -1e30f;
        __syncthreads();

        float s[8][4];
#pragma unroll
        for (int i = 0; i < 8; ++i)
#pragma unroll
            for (int j = 0; j < 4; ++j) s[i][j] = 0.f;

#pragma unroll 4
        for (int d = 0; d < 64; ++d) {
            float4 a0 = *(const float4*)&Qt[d * 132 + ty * 4];
            float4 a1 = *(const float4*)&Qt[d * 132 + ty * 4 + 64];
            float4 bk4 = *(const float4*)&Kt[d * 68 + tx * 4];
            float ar[8] = {a0.x, a0.y, a0.z, a0.w, a1.x, a1.y, a1.z, a1.w};
            float br[4] = {bk4.x, bk4.y, bk4.z, bk4.w};
#pragma unroll
            for (int i = 0; i < 8; ++i)
#pragma unroll
                for (int j = 0; j < 4; ++j)
                    s[i][j] = fmaf(ar[i], br[j], s[i][j]);
        }

#pragma unroll
        for (int i = 0; i < 8; ++i) {
            const int row = (i < 4) ? (ty * 4 + i) : (64 + ty * 4 + i - 4);
            float mx = -1e30f;
#pragma unroll
            for (int j = 0; j < 4; ++j) {
                s[i][j] += mb[tx * 4 + j];
                mx = fmaxf(mx, s[i][j]);
            }
            red[row * 17 + tx] = mx;
        }
        __syncthreads();

        if (tid < 128) {
            float mx = red[tid * 17];
#pragma unroll
            for (int t = 1; t < 16; ++t) mx = fmaxf(mx, red[tid * 17 + t]);
            const float mnew = fmaxf(m_i[tid], mx);
            corr[tid] = __expf(m_i[tid] - mnew);
            m_i[tid] = mnew;
        }
        __syncthreads();

#pragma unroll
        for (int i = 0; i < 8; ++i) {
            const int row = (i < 4) ? (ty * 4 + i) : (64 + ty * 4 + i - 4);
            const float mn = m_i[row];
            const float c  = corr[row];
            float sum = 0.f;
#pragma unroll
            for (int j = 0; j < 4; ++j) {
                const float p = __expf(s[i][j] - mn);
                sum += p;
                acc[i][j] *= c;
                Pt[(tx * 4 + j) * 132 + row] = p;
            }
            red[row * 17 + tx] = sum;
        }
        __syncthreads();

        if (tid < 128) {
            float sum = 0.f;
#pragma unroll
            for (int t = 0; t < 16; ++t) sum += red[tid * 17 + t];
            l_i[tid] = l_i[tid] * corr[tid] + sum;
        }

#pragma unroll 2
        for (int kk = 0; kk < 64; ++kk) {
            float4 p0 = *(const float4*)&Pt[kk * 132 + ty * 4];
            float4 p1 = *(const float4*)&Pt[kk * 132 + ty * 4 + 64];
            float4 vv = *(const float4*)&Vs[kk * 68 + tx * 4];
            float pr[8] = {p0.x, p0.y, p0.z, p0.w, p1.x, p1.y, p1.z, p1.w};
            float vr[4] = {vv.x, vv.y, vv.z, vv.w};
#pragma unroll
            for (int i = 0; i < 8; ++i)
#pragma unroll
                for (int j = 0; j < 4; ++j)
                    acc[i][j] = fmaf(pr[i], vr[j], acc[i][j]);
        }
        __syncthreads();
    }

#pragma unroll
    for (int i = 0; i < 8; ++i) {
        const int row = (i < 4) ? (ty * 4 + i) : (64 + ty * 4 + i - 4);
        const float inv = 1.f / l_i[row];
        float2 dummy; (void)dummy;
        float4 o;
        o.x = acc[i][0] * inv;
        o.y = acc[i][1] * inv;
        o.z = acc[i][2] * inv;
        o.w = acc[i][3] * inv;
        *(float4*)&out[(size_t)(b * SEQ + q0 + row) * DIM + h * HDIM + tx * 4] = o;
    }
}

// ---------------- LayerNorm: one block per row ----------------
__global__ __launch_bounds__(256) void ln_kernel(const float* __restrict__ in,
                                                 const float* __restrict__ gam,
                                                 const float* __restrict__ bet,
                                                 float* __restrict__ out)
{
    const int row = blockIdx.x;
    const int tid = threadIdx.x;
    const float* x = in + (size_t)row * DIM;

    float v[3];
    float s = 0.f, s2 = 0.f;
#pragma unroll
    for (int i = 0; i < 3; ++i) {
        v[i] = x[tid + i * 256];
        s  += v[i];
        s2 += v[i] * v[i];
    }
#pragma unroll
    for (int o = 16; o > 0; o >>= 1) {
        s  += __shfl_xor_sync(0xffffffffu, s,  o);
        s2 += __shfl_xor_sync(0xffffffffu, s2, o);
    }
    __shared__ float sh[18];
    const int wid = tid >> 5, lane = tid & 31;
    if (lane == 0) { sh[wid] = s; sh[8 + wid] = s2; }
    __syncthreads();
    if (tid == 0) {
        float ts = 0.f, ts2 = 0.f;
#pragma unroll
        for (int w = 0; w < 8; ++w) { ts += sh[w]; ts2 += sh[8 + w]; }
        const float mu  = ts * (1.f / DIM);
        const float var = ts2 * (1.f / DIM) - mu * mu;
        sh[16] = mu;
        sh[17] = rsqrtf(var + 1e-6f);
    }
    __syncthreads();
    const float mu = sh[16], rstd = sh[17];
#pragma unroll
    for (int i = 0; i < 3; ++i) {
        const int d = tid + i * 256;
        out[(size_t)row * DIM + d] = (v[i] - mu) * rstd * gam[d] + bet[d];
    }
}

// ---------------- launch ----------------
extern "C" void kernel_launch(void* const* d_in, const int* in_sizes, int n_in,
                              void* d_out, int out_size)
{
    const float* x    = (const float*)d_in[0];
    const int*   mask = (const int*)  d_in[1];
    const float* Wq   = (const float*)d_in[2];
    const float* bq   = (const float*)d_in[3];
    const float* Wk   = (const float*)d_in[4];
    const float* bk   = (const float*)d_in[5];
    const float* Wv   = (const float*)d_in[6];
    const float* bv   = (const float*)d_in[7];
    const float* Wo   = (const float*)d_in[8];
    const float* bo   = (const float*)d_in[9];
    const float* W1   = (const float*)d_in[10];
    const float* b1   = (const float*)d_in[11];
    const float* W2   = (const float*)d_in[12];
    const float* b2   = (const float*)d_in[13];
    const float* g1   = (const float*)d_in[14];
    const float* be1  = (const float*)d_in[15];
    const float* g2   = (const float*)d_in[16];
    const float* be2  = (const float*)d_in[17];
    float* out = (float*)d_out;

    float *q, *k, *v, *attn, *t1, *h, *ff;
    cudaGetSymbolAddress((void**)&q,    g_q);
    cudaGetSymbolAddress((void**)&k,    g_k);
    cudaGetSymbolAddress((void**)&v,    g_v);
    cudaGetSymbolAddress((void**)&attn, g_attn);
    cudaGetSymbolAddress((void**)&t1,   g_t1);
    cudaGetSymbolAddress((void**)&h,    g_h);
    cudaGetSymbolAddress((void**)&ff,   g_ff);

    static bool attr_done = false;
    if (!attr_done) {
        cudaFuncSetAttribute(tgemm<1>, cudaFuncAttributeMaxDynamicSharedMemorySize, GEMM_SMEM);
        cudaFuncSetAttribute(tgemm<2>, cudaFuncAttributeMaxDynamicSharedMemorySize, GEMM_SMEM);
        cudaFuncSetAttribute(tgemm<3>, cudaFuncAttributeMaxDynamicSharedMemorySize, GEMM_SMEM);
        cudaFuncSetAttribute(attn_kernel, cudaFuncAttributeMaxDynamicSharedMemorySize,
                             ATTN_SMEM_FLOATS * (int)sizeof(float));
        attr_done = true;
    }

    const dim3 gD(DIM / 128, ROWS / 128);     // (6, 64)
    const dim3 gF(FFDIM / 128, ROWS / 128);   // (24, 64)

    // QKV projections, stored as [B,H,S,HD]
    tgemm<1><<<gD, 256, GEMM_SMEM>>>(x, Wq, bq, nullptr, q, ROWS, DIM, DIM);
    tgemm<1><<<gD, 256, GEMM_SMEM>>>(x, Wk, bk, nullptr, k, ROWS, DIM, DIM);
    tgemm<1><<<gD, 256, GEMM_SMEM>>>(x, Wv, bv, nullptr, v, ROWS, DIM, DIM);

    // flash attention
    const int smem_bytes = ATTN_SMEM_FLOATS * (int)sizeof(float);
    attn_kernel<<<BATCH * NH * (SEQ / 128), 256, smem_bytes>>>(q, k, v, mask, attn);

    // O projection + residual, LN1
    tgemm<3><<<gD, 256, GEMM_SMEM>>>(attn, Wo, bo, x, t1, ROWS, DIM, DIM);
    ln_kernel<<<ROWS, 256>>>(t1, g1, be1, h);

    // FFN
    tgemm<2><<<gF, 256, GEMM_SMEM>>>(h, W1, b1, nullptr, ff, ROWS, FFDIM, DIM);
    tgemm<3><<<gD, 256, GEMM_SMEM>>>(ff, W2, b2, h, t1, ROWS, DIM, FFDIM);
    ln_kernel<<<ROWS, 256>>>(t1, g2, be2, out);
}

// round 3
// speedup vs baseline: 2.8191x; 1.5470x over previous
#include <cuda_runtime.h>
#include <math.h>

#define BATCH 4
#define SEQ   2048
#define DIM   768
#define NH    12
#define HDIM  64
#define FFDIM (4*DIM)
#define ROWS  (BATCH*SEQ)   /* 8192 */

// ---------------- scratch (no cudaMalloc allowed) ----------------
__device__ float g_q[(size_t)BATCH*NH*SEQ*HDIM];
__device__ float g_k[(size_t)BATCH*NH*SEQ*HDIM];
__device__ float g_v[(size_t)BATCH*NH*SEQ*HDIM];
__device__ float g_attn[(size_t)ROWS*DIM];
__device__ float g_t1[(size_t)ROWS*DIM];
__device__ float g_h[(size_t)ROWS*DIM];
__device__ float g_ff[(size_t)ROWS*FFDIM];

__device__ __forceinline__ unsigned f2tf(float f) {
    unsigned r;
    asm("cvt.rna.tf32.f32 %0, %1;" : "=r"(r) : "f"(f));
    return r;
}

__device__ __forceinline__ void mma_tf32(float* d, const unsigned* a, const unsigned* b) {
    asm volatile(
        "mma.sync.aligned.m16n8k8.row.col.f32.tf32.tf32.f32 "
        "{%0,%1,%2,%3}, {%4,%5,%6,%7}, {%8,%9}, {%0,%1,%2,%3};\n"
        : "+f"(d[0]), "+f"(d[1]), "+f"(d[2]), "+f"(d[3])
        : "r"(a[0]), "r"(a[1]), "r"(a[2]), "r"(a[3]), "r"(b[0]), "r"(b[1]));
}

// ======================================================================
// TF32 tensor-core GEMM (unchanged from R2): 128x128 tile, BK=32, 8 warps
// MODE 0: +bias  1: QKV permuted store  2: gelu  3: +bias+res
// ======================================================================
#define SA 36
#define SB 136
#define ABUF (128*SA)
#define BBUF (32*SB)
#define BUFSZ (ABUF + BBUF)

template<int MODE>
__global__ __launch_bounds__(256) void tgemm(const float* __restrict__ A,
                                             const float* __restrict__ B,
                                             const float* __restrict__ bias,
                                             const float* __restrict__ res,
                                             float* __restrict__ C,
                                             int M, int N, int K)
{
    extern __shared__ float sm[];

    const int tid  = threadIdx.x;
    const int lane = tid & 31;
    const int warp = tid >> 5;
    const int wr   = warp >> 2;
    const int wn   = warp & 3;
    const int bm   = blockIdx.y * 128;
    const int bn   = blockIdx.x * 128;

    const int arow = tid >> 3;
    const int acol = (tid & 7) * 4;
    const int bkr  = tid >> 5;
    const int bcol = (tid & 31) * 4;

    float acc[4][4][4];
#pragma unroll
    for (int mt = 0; mt < 4; ++mt)
#pragma unroll
        for (int nt = 0; nt < 4; ++nt)
#pragma unroll
            for (int e = 0; e < 4; ++e) acc[mt][nt][e] = 0.f;

    const int nk = K >> 5;
    float4 ra[4], rb[4];

    {
        const float* Ap = A + (size_t)(bm + arow) * K + acol;
        const float* Bp = B + (size_t)bkr * N + bn + bcol;
#pragma unroll
        for (int i = 0; i < 4; ++i) {
            ra[i] = *(const float4*)(Ap + (size_t)(32 * i) * K);
            rb[i] = *(const float4*)(Bp + (size_t)(8 * i) * N);
        }
    }
    {
        float* As = sm;
        float* Bs = sm + ABUF;
#pragma unroll
        for (int i = 0; i < 4; ++i) {
            unsigned x = f2tf(ra[i].x), y = f2tf(ra[i].y), z = f2tf(ra[i].z), w = f2tf(ra[i].w);
            float4 v = make_float4(__uint_as_float(x), __uint_as_float(y),
                                   __uint_as_float(z), __uint_as_float(w));
            *(float4*)&As[(arow + 32 * i) * SA + acol] = v;
            x = f2tf(rb[i].x); y = f2tf(rb[i].y); z = f2tf(rb[i].z); w = f2tf(rb[i].w);
            v = make_float4(__uint_as_float(x), __uint_as_float(y),
                            __uint_as_float(z), __uint_as_float(w));
            *(float4*)&Bs[(bkr + 8 * i) * SB + bcol] = v;
        }
    }
    __syncthreads();

    for (int t = 0; t < nk; ++t) {
        if (t + 1 < nk) {
            const float* Ap = A + (size_t)(bm + arow) * K + (t + 1) * 32 + acol;
            const float* Bp = B + (size_t)((t + 1) * 32 + bkr) * N + bn + bcol;
#pragma unroll
            for (int i = 0; i < 4; ++i) {
                ra[i] = *(const float4*)(Ap + (size_t)(32 * i) * K);
                rb[i] = *(const float4*)(Bp + (size_t)(8 * i) * N);
            }
        }
        {
            const float* As = sm + (t & 1) * BUFSZ;
            const float* Bs = As + ABUF;
#pragma unroll
            for (int ks = 0; ks < 4; ++ks) {
                const int k0 = ks * 8 + (lane & 3);
                unsigned af[4][4], bf[4][2];
#pragma unroll
                for (int mt = 0; mt < 4; ++mt) {
                    const int m0 = wr * 64 + mt * 16 + (lane >> 2);
                    af[mt][0] = __float_as_uint(As[m0 * SA + k0]);
                    af[mt][1] = __float_as_uint(As[(m0 + 8) * SA + k0]);
                    af[mt][2] = __float_as_uint(As[m0 * SA + k0 + 4]);
                    af[mt][3] = __float_as_uint(As[(m0 + 8) * SA + k0 + 4]);
                }
#pragma unroll
                for (int nt = 0; nt < 4; ++nt) {
                    const int n0 = wn * 32 + nt * 8 + (lane >> 2);
                    bf[nt][0] = __float_as_uint(Bs[k0 * SB + n0]);
                    bf[nt][1] = __float_as_uint(Bs[(k0 + 4) * SB + n0]);
                }
#pragma unroll
                for (int mt = 0; mt < 4; ++mt)
#pragma unroll
                    for (int nt = 0; nt < 4; ++nt)
                        mma_tf32(acc[mt][nt], af[mt], bf[nt]);
            }
        }
        if (t + 1 < nk) {
            float* As = sm + ((t + 1) & 1) * BUFSZ;
            float* Bs = As + ABUF;
#pragma unroll
            for (int i = 0; i < 4; ++i) {
                unsigned x = f2tf(ra[i].x), y = f2tf(ra[i].y), z = f2tf(ra[i].z), w = f2tf(ra[i].w);
                float4 v = make_float4(__uint_as_float(x), __uint_as_float(y),
                                       __uint_as_float(z), __uint_as_float(w));
                *(float4*)&As[(arow + 32 * i) * SA + acol] = v;
                x = f2tf(rb[i].x); y = f2tf(rb[i].y); z = f2tf(rb[i].z); w = f2tf(rb[i].w);
                v = make_float4(__uint_as_float(x), __uint_as_float(y),
                                __uint_as_float(z), __uint_as_float(w));
                *(float4*)&Bs[(bkr + 8 * i) * SB + bcol] = v;
            }
            __syncthreads();
        }
    }

#pragma unroll
    for (int mt = 0; mt < 4; ++mt) {
        const int row_lo = bm + wr * 64 + mt * 16 + (lane >> 2);
#pragma unroll
        for (int nt = 0; nt < 4; ++nt) {
            const int col = bn + wn * 32 + nt * 8 + (lane & 3) * 2;
#pragma unroll
            for (int half = 0; half < 2; ++half) {
                const int row = row_lo + half * 8;
                float2 v;
                v.x = acc[mt][nt][half * 2 + 0] + bias[col + 0];
                v.y = acc[mt][nt][half * 2 + 1] + bias[col + 1];
                if (MODE == 2) {
                    v.x = 0.5f * v.x * (1.f + erff(v.x * 0.70710678118654752f));
                    v.y = 0.5f * v.y * (1.f + erff(v.y * 0.70710678118654752f));
                }
                if (MODE == 3) {
                    float2 r = *(const float2*)&res[(size_t)row * N + col];
                    v.x += r.x; v.y += r.y;
                }
                if (MODE == 1) {
                    const int b = row / SEQ, s = row % SEQ;
                    const int h = col / HDIM, hd = col % HDIM;
                    *(float2*)&C[(((size_t)b * NH + h) * SEQ + s) * HDIM + hd] = v;
                } else {
                    *(float2*)&C[(size_t)row * N + col] = v;
                }
            }
        }
    }
}

#define GEMM_SMEM (2 * BUFSZ * (int)sizeof(float))

// ======================================================================
// TF32 tensor-core flash attention
// BM=128 (8 warps x 16 rows), BN=64 keys/tile, HD=64.
// Kt: d-major [64][72], Vs: key-major [64][72], Ps: per-warp [16][68].
// ======================================================================
#define SK 72
#define SP 68
#define ATT_SMEM_FLOATS (64*SK + 64*SK + 8*16*SP + 64)
#define ATT_SMEM (ATT_SMEM_FLOATS * (int)sizeof(float))

__global__ __launch_bounds__(256) void attn_tc(const float* __restrict__ q,
                                               const float* __restrict__ k,
                                               const float* __restrict__ v,
                                               const int* __restrict__ mask,
                                               float* __restrict__ out)
{
    extern __shared__ float sm[];
    float* Kt = sm;                    // [d][key]  64*72
    float* Vs = Kt + 64 * SK;          // [key][d]  64*72
    float* Ps = Vs + 64 * SK;          // 8 warps x [16][68]
    float* mb = Ps + 8 * 16 * SP;      // [64]

    const int tid  = threadIdx.x;
    const int lane = tid & 31;
    const int warp = tid >> 5;

    const int qtile = blockIdx.x & 15;
    const int bh    = blockIdx.x >> 4;
    const int b     = bh / NH;
    const int h     = bh % NH;
    const float scale = 0.125f;

    const size_t base = (size_t)bh * SEQ * HDIM;
    const int q0 = qtile * 128;

    const int r0 = lane >> 2;     // 0..7
    const int kq = lane & 3;      // 0..3

    // ---- Q fragments (register resident, scaled, tf32) ----
    unsigned qa[8][4];
    {
        const float* qp = q + base + (size_t)(q0 + warp * 16) * HDIM;
#pragma unroll
        for (int c = 0; c < 8; ++c) {
            qa[c][0] = f2tf(qp[(size_t)r0 * HDIM + c * 8 + kq] * scale);
            qa[c][1] = f2tf(qp[(size_t)(r0 + 8) * HDIM + c * 8 + kq] * scale);
            qa[c][2] = f2tf(qp[(size_t)r0 * HDIM + c * 8 + kq + 4] * scale);
            qa[c][3] = f2tf(qp[(size_t)(r0 + 8) * HDIM + c * 8 + kq + 4] * scale);
        }
    }

    float m_i[2] = {-1e30f, -1e30f};
    float l_i[2] = {0.f, 0.f};
    float oacc[8][4];
#pragma unroll
    for (int nt = 0; nt < 8; ++nt)
#pragma unroll
        for (int e = 0; e < 4; ++e) oacc[nt][e] = 0.f;

    float* Pw = Ps + warp * 16 * SP;

    const int key = tid & 63;
    const int dc  = tid >> 6;     // 0..3

    for (int kt = 0; kt < SEQ / 64; ++kt) {
        const int k0g = kt * 64;
        __syncthreads();   // protect Kt/Vs from previous iteration readers

        // ---- load K (transposed to d-major) and V (row-major), tf32 ----
        {
            const float* kp = k + base + (size_t)(k0g + key) * HDIM + dc * 16;
            const float* vp = v + base + (size_t)(k0g + key) * HDIM + dc * 16;
#pragma unroll
            for (int i = 0; i < 4; ++i) {
                const int d = dc * 16 + i * 4;
                float4 kv = *(const float4*)(kp + i * 4);
                Kt[(d + 0) * SK + key] = __uint_as_float(f2tf(kv.x));
                Kt[(d + 1) * SK + key] = __uint_as_float(f2tf(kv.y));
                Kt[(d + 2) * SK + key] = __uint_as_float(f2tf(kv.z));
                Kt[(d + 3) * SK + key] = __uint_as_float(f2tf(kv.w));
                float4 vv = *(const float4*)(vp + i * 4);
                float4 vt = make_float4(__uint_as_float(f2tf(vv.x)), __uint_as_float(f2tf(vv.y)),
                                        __uint_as_float(f2tf(vv.z)), __uint_as_float(f2tf(vv.w)));
                *(float4*)&Vs[key * SK + d] = vt;
            }
        }
        if (tid < 64) mb[tid] = mask[b * SEQ + k0g + tid] ? 0.f : -1e30f;
        __syncthreads();

        // ---- S = Q @ K^T ----
        float sf[8][4];
#pragma unroll
        for (int nt = 0; nt < 8; ++nt)
#pragma unroll
            for (int e = 0; e < 4; ++e) sf[nt][e] = 0.f;

#pragma unroll
        for (int nt = 0; nt < 8; ++nt) {
            const int n0 = nt * 8 + r0;
#pragma unroll
            for (int c = 0; c < 8; ++c) {
                unsigned bf[2];
                bf[0] = __float_as_uint(Kt[(c * 8 + kq) * SK + n0]);
                bf[1] = __float_as_uint(Kt[(c * 8 + kq + 4) * SK + n0]);
                mma_tf32(sf[nt], qa[c], bf);
            }
        }

        // ---- softmax (registers + quad shuffles) ----
        float mx0 = -1e30f, mx1 = -1e30f;
#pragma unroll
        for (int nt = 0; nt < 8; ++nt) {
            float2 mbv = *(const float2*)&mb[nt * 8 + kq * 2];
            sf[nt][0] += mbv.x; sf[nt][1] += mbv.y;
            sf[nt][2] += mbv.x; sf[nt][3] += mbv.y;
            mx0 = fmaxf(mx0, fmaxf(sf[nt][0], sf[nt][1]));
            mx1 = fmaxf(mx1, fmaxf(sf[nt][2], sf[nt][3]));
        }
        mx0 = fmaxf(mx0, __shfl_xor_sync(0xffffffffu, mx0, 1));
        mx0 = fmaxf(mx0, __shfl_xor_sync(0xffffffffu, mx0, 2));
        mx1 = fmaxf(mx1, __shfl_xor_sync(0xffffffffu, mx1, 1));
        mx1 = fmaxf(mx1, __shfl_xor_sync(0xffffffffu, mx1, 2));

        const float mn0 = fmaxf(m_i[0], mx0);
        const float mn1 = fmaxf(m_i[1], mx1);
        const float cr0 = __expf(m_i[0] - mn0);
        const float cr1 = __expf(m_i[1] - mn1);
        m_i[0] = mn0; m_i[1] = mn1;

        float sum0 = 0.f, sum1 = 0.f;
#pragma unroll
        for (int nt = 0; nt < 8; ++nt) {
            const float p0 = __expf(sf[nt][0] - mn0);
            const float p1 = __expf(sf[nt][1] - mn0);
            const float p2 = __expf(sf[nt][2] - mn1);
            const float p3 = __expf(sf[nt][3] - mn1);
            sum0 += p0 + p1;
            sum1 += p2 + p3;
            float2 lo = make_float2(__uint_as_float(f2tf(p0)), __uint_as_float(f2tf(p1)));
            float2 hi = make_float2(__uint_as_float(f2tf(p2)), __uint_as_float(f2tf(p3)));
            *(float2*)&Pw[r0 * SP + nt * 8 + kq * 2] = lo;
            *(float2*)&Pw[(r0 + 8) * SP + nt * 8 + kq * 2] = hi;
        }
        sum0 += __shfl_xor_sync(0xffffffffu, sum0, 1);
        sum0 += __shfl_xor_sync(0xffffffffu, sum0, 2);
        sum1 += __shfl_xor_sync(0xffffffffu, sum1, 1);
        sum1 += __shfl_xor_sync(0xffffffffu, sum1, 2);
        l_i[0] = l_i[0] * cr0 + sum0;
        l_i[1] = l_i[1] * cr1 + sum1;

#pragma unroll
        for (int nt = 0; nt < 8; ++nt) {
            oacc[nt][0] *= cr0; oacc[nt][1] *= cr0;
            oacc[nt][2] *= cr1; oacc[nt][3] *= cr1;
        }

        __syncwarp();

        // ---- O += P @ V ----
        unsigned pa[8][4];
#pragma unroll
        for (int c = 0; c < 8; ++c) {
            pa[c][0] = __float_as_uint(Pw[r0 * SP + c * 8 + kq]);
            pa[c][1] = __float_as_uint(Pw[(r0 + 8) * SP + c * 8 + kq]);
            pa[c][2] = __float_as_uint(Pw[r0 * SP + c * 8 + kq + 4]);
            pa[c][3] = __float_as_uint(Pw[(r0 + 8) * SP + c * 8 + kq + 4]);
        }
#pragma unroll
        for (int nt = 0; nt < 8; ++nt) {
            const int n0 = nt * 8 + r0;
#pragma unroll
            for (int c = 0; c < 8; ++c) {
                unsigned bf[2];
                bf[0] = __float_as_uint(Vs[(c * 8 + kq) * SK + n0]);
                bf[1] = __float_as_uint(Vs[(c * 8 + kq + 4) * SK + n0]);
                mma_tf32(oacc[nt], pa[c], bf);
            }
        }
    }

    // ---- epilogue: O /= l, write [B,S,D] ----
    const float inv0 = 1.f / l_i[0];
    const float inv1 = 1.f / l_i[1];
    const int row_g = q0 + warp * 16 + r0;
#pragma unroll
    for (int nt = 0; nt < 8; ++nt) {
        const int col = h * HDIM + nt * 8 + kq * 2;
        float2 lo = make_float2(oacc[nt][0] * inv0, oacc[nt][1] * inv0);
        float2 hi = make_float2(oacc[nt][2] * inv1, oacc[nt][3] * inv1);
        *(float2*)&out[(size_t)(b * SEQ + row_g) * DIM + col] = lo;
        *(float2*)&out[(size_t)(b * SEQ + row_g + 8) * DIM + col] = hi;
    }
}

// ---------------- LayerNorm: one block per row ----------------
__global__ __launch_bounds__(256) void ln_kernel(const float* __restrict__ in,
                                                 const float* __restrict__ gam,
                                                 const float* __restrict__ bet,
                                                 float* __restrict__ out)
{
    const int row = blockIdx.x;
    const int tid = threadIdx.x;
    const float* x = in + (size_t)row * DIM;

    float v[3];
    float s = 0.f, s2 = 0.f;
#pragma unroll
    for (int i = 0; i < 3; ++i) {
        v[i] = x[tid + i * 256];
        s  += v[i];
        s2 += v[i] * v[i];
    }
#pragma unroll
    for (int o = 16; o > 0; o >>= 1) {
        s  += __shfl_xor_sync(0xffffffffu, s,  o);
        s2 += __shfl_xor_sync(0xffffffffu, s2, o);
    }
    __shared__ float sh[18];
    const int wid = tid >> 5, lane = tid & 31;
    if (lane == 0) { sh[wid] = s; sh[8 + wid] = s2; }
    __syncthreads();
    if (tid == 0) {
        float ts = 0.f, ts2 = 0.f;
#pragma unroll
        for (int w = 0; w < 8; ++w) { ts += sh[w]; ts2 += sh[8 + w]; }
        const float mu  = ts * (1.f / DIM);
        const float var = ts2 * (1.f / DIM) - mu * mu;
        sh[16] = mu;
        sh[17] = rsqrtf(var + 1e-6f);
    }
    __syncthreads();
    const float mu = sh[16], rstd = sh[17];
#pragma unroll
    for (int i = 0; i < 3; ++i) {
        const int d = tid + i * 256;
        out[(size_t)row * DIM + d] = (v[i] - mu) * rstd * gam[d] + bet[d];
    }
}

// ---------------- launch ----------------
extern "C" void kernel_launch(void* const* d_in, const int* in_sizes, int n_in,
                              void* d_out, int out_size)
{
    const float* x    = (const float*)d_in[0];
    const int*   mask = (const int*)  d_in[1];
    const float* Wq   = (const float*)d_in[2];
    const float* bq   = (const float*)d_in[3];
    const float* Wk   = (const float*)d_in[4];
    const float* bk   = (const float*)d_in[5];
    const float* Wv   = (const float*)d_in[6];
    const float* bv   = (const float*)d_in[7];
    const float* Wo   = (const float*)d_in[8];
    const float* bo   = (const float*)d_in[9];
    const float* W1   = (const float*)d_in[10];
    const float* b1   = (const float*)d_in[11];
    const float* W2   = (const float*)d_in[12];
    const float* b2   = (const float*)d_in[13];
    const float* g1   = (const float*)d_in[14];
    const float* be1  = (const float*)d_in[15];
    const float* g2   = (const float*)d_in[16];
    const float* be2  = (const float*)d_in[17];
    float* out = (float*)d_out;

    float *q, *k, *v, *attn, *t1, *h, *ff;
    cudaGetSymbolAddress((void**)&q,    g_q);
    cudaGetSymbolAddress((void**)&k,    g_k);
    cudaGetSymbolAddress((void**)&v,    g_v);
    cudaGetSymbolAddress((void**)&attn, g_attn);
    cudaGetSymbolAddress((void**)&t1,   g_t1);
    cudaGetSymbolAddress((void**)&h,    g_h);
    cudaGetSymbolAddress((void**)&ff,   g_ff);

    static bool attr_done = false;
    if (!attr_done) {
        cudaFuncSetAttribute(tgemm<1>, cudaFuncAttributeMaxDynamicSharedMemorySize, GEMM_SMEM);
        cudaFuncSetAttribute(tgemm<2>, cudaFuncAttributeMaxDynamicSharedMemorySize, GEMM_SMEM);
        cudaFuncSetAttribute(tgemm<3>, cudaFuncAttributeMaxDynamicSharedMemorySize, GEMM_SMEM);
        cudaFuncSetAttribute(attn_tc, cudaFuncAttributeMaxDynamicSharedMemorySize, ATT_SMEM);
        attr_done = true;
    }

    const dim3 gD(DIM / 128, ROWS / 128);     // (6, 64)
    const dim3 gF(FFDIM / 128, ROWS / 128);   // (24, 64)

    // QKV projections, stored as [B,H,S,HD]
    tgemm<1><<<gD, 256, GEMM_SMEM>>>(x, Wq, bq, nullptr, q, ROWS, DIM, DIM);
    tgemm<1><<<gD, 256, GEMM_SMEM>>>(x, Wk, bk, nullptr, k, ROWS, DIM, DIM);
    tgemm<1><<<gD, 256, GEMM_SMEM>>>(x, Wv, bv, nullptr, v, ROWS, DIM, DIM);

    // tensor-core flash attention
    attn_tc<<<BATCH * NH * (SEQ / 128), 256, ATT_SMEM>>>(q, k, v, mask, attn);

    // O projection + residual, LN1
    tgemm<3><<<gD, 256, GEMM_SMEM>>>(attn, Wo, bo, x, t1, ROWS, DIM, DIM);
    ln_kernel<<<ROWS, 256>>>(t1, g1, be1, h);

    // FFN
    tgemm<2><<<gF, 256, GEMM_SMEM>>>(h, W1, b1, nullptr, ff, ROWS, FFDIM, DIM);
    tgemm<3><<<gD, 256, GEMM_SMEM>>>(ff, W2, b2, h, t1, ROWS, DIM, FFDIM);
    ln_kernel<<<ROWS, 256>>>(t1, g2, be2, out);
}